// round 15
// baseline (speedup 1.0000x reference)
#include <cuda_runtime.h>
#include <cuda_bf16.h>
#include <cstdint>

// ---------------- problem constants ----------------
#define N_ROWS  65536
#define D_LAT   64
#define KC      64
#define D_DATA  512
#define N_ITERS 10

#define TILE     128
#define GRID_IT  256
#define TPB      2                     // tiles per block
#define BLK      384                   // 12 warps: 8 compute + 4 dec-streamer

// smem float offsets
#define SF_C2    0                      // [64]
#define SF_RED   64                     // [384]
#define SF_X2    448                    // [256]
#define SF_ENC   704                    // f32 [128][76] (gemm2 B + ones cols)
#define SF_ENCH  (SF_ENC + 128*76)      // u32 bf16x2 [128][36] (gemm1 A)
#define SF_CH    (SF_ENCH + 128*36)     // u32 bf16x2 [64][36]  (gemm1 B: C row-major)
#define SF_R     (SF_CH + 64*36)        // f32 [128][72]
#define SF_TOT   (SF_R + 128*72)        // 26560 floats = 106240 B  (2 CTA/SM OK)

// ---------------- scratch globals ----------------
__device__ float g_C[KC * D_LAT];
__device__ float g_partC[GRID_IT * KC * D_LAT];
__device__ float g_partR[GRID_IT * KC];
__device__ float g_partLoss[GRID_IT];
__device__ float g_decPart[GRID_IT];

// grid barrier (returns to initial state after each full barrier)
__device__ unsigned g_barArr = 0;
__device__ volatile unsigned g_barGen = 0;

__device__ __forceinline__ void gridBar() {
    __syncthreads();
    if (threadIdx.x == 0) {
        __threadfence();
        unsigned gen = g_barGen;
        if (atomicAdd(&g_barArr, 1u) == GRID_IT - 1) {
            g_barArr = 0;
            __threadfence();
            g_barGen = gen + 1;
        } else {
            while (g_barGen == gen) { __nanosleep(64); }
            __threadfence();
        }
    }
    __syncthreads();
}

// ---------------- mma.sync wrappers ----------------
__device__ __forceinline__ void mma_tf32(float* c, uint32_t a0, uint32_t a1,
                                         uint32_t a2, uint32_t a3,
                                         uint32_t b0, uint32_t b1) {
    asm volatile(
        "mma.sync.aligned.m16n8k8.row.col.f32.tf32.tf32.f32 "
        "{%0,%1,%2,%3}, {%4,%5,%6,%7}, {%8,%9}, {%0,%1,%2,%3};"
        : "+f"(c[0]), "+f"(c[1]), "+f"(c[2]), "+f"(c[3])
        : "r"(a0), "r"(a1), "r"(a2), "r"(a3), "r"(b0), "r"(b1));
}
__device__ __forceinline__ void mma_bf16(float* c, uint32_t a0, uint32_t a1,
                                         uint32_t a2, uint32_t a3,
                                         uint32_t b0, uint32_t b1) {
    asm volatile(
        "mma.sync.aligned.m16n8k16.row.col.f32.bf16.bf16.f32 "
        "{%0,%1,%2,%3}, {%4,%5,%6,%7}, {%8,%9}, {%0,%1,%2,%3};"
        : "+f"(c[0]), "+f"(c[1]), "+f"(c[2]), "+f"(c[3])
        : "r"(a0), "r"(a1), "r"(a2), "r"(a3), "r"(b0), "r"(b1));
}
__device__ __forceinline__ uint32_t fb(float x) { return __float_as_uint(x); }
__device__ __forceinline__ uint32_t packbf(float x, float y) {
    __nv_bfloat162 h = __float22bfloat162_rn(make_float2(x, y));
    return *reinterpret_cast<uint32_t*>(&h);
}

// ---------------- one persistent kernel ----------------
__global__ void __launch_bounds__(BLK, 2)
fused_kernel(const float* __restrict__ enc,
             const float* __restrict__ X, const float* __restrict__ dec,
             float* __restrict__ out) {
    extern __shared__ float sm[];
    float* sC2  = sm + SF_C2;
    float* sRed = sm + SF_RED;
    float* sX2  = sm + SF_X2;
    float* sEnc = sm + SF_ENC;
    uint32_t* sEncH = reinterpret_cast<uint32_t*>(sm + SF_ENCH);
    uint32_t* sCH   = reinterpret_cast<uint32_t*>(sm + SF_CH);
    float* sR   = sm + SF_R;

    int t = threadIdx.x, w = t >> 5, lane = t & 31;
    int bid = blockIdx.x;
    int qr = lane >> 2, qc = lane & 3;
    bool isCompute = (w < 8);
    int dt = t - 256;                  // dec-warp lane index (0..127)

    // ---- prologue: x2 for this block's 256 rows; ones cols for gemm2 ----
    if (isCompute) {
        int rowBase = bid * 256 + w * 32;
        for (int i = 0; i < 32; i++) {
            const float2* e = reinterpret_cast<const float2*>(enc + (size_t)(rowBase + i) * D_LAT);
            float2 v = e[lane];
            float s = v.x * v.x + v.y * v.y;
            #pragma unroll
            for (int off = 16; off; off >>= 1) s += __shfl_xor_sync(0xffffffffu, s, off);
            if (lane == 0) sX2[w * 32 + i] = s;
        }
    }
    if (t < 128) {
        sEnc[t * 76 + 64] = 1.0f;
        #pragma unroll
        for (int c = 65; c < 72; c++) sEnc[t * 76 + c] = 0.0f;
    }

    int m2  = (w & 3) * 16;            // gemm2 m-tile base
    int nb2 = w >> 2;                  // gemm2 n-tile family {nb2, nb2+3, nb2+6}

    float decAcc = 0.f, lossAcc = 0.f;
    const int total4 = (N_ROWS * D_DATA) / 4;
    const int chunk = (total4 + N_ITERS - 1) / N_ITERS;
    const float4* x4 = reinterpret_cast<const float4*>(X);
    const float4* d4 = reinterpret_cast<const float4*>(dec);

    for (int it = 0; it < N_ITERS; it++) {
        int doUpdate = (it < N_ITERS - 1);
        int doLoss   = (it == N_ITERS - 1);

        const float* csrc = (it == 0) ? enc : g_C;
        __syncthreads();

        // ---- fill sCH: C row-major bf16, d-pairs packed (stride 36 b32) ----
        for (int idx = t; idx < 2048; idx += BLK) {
            int k = idx >> 5, dp = idx & 31;
            float2 cv = *reinterpret_cast<const float2*>(&csrc[k * 64 + dp * 2]);
            sCH[k * 36 + dp] = packbf(cv.x, cv.y);
        }
        // ---- c2 partials from f32 source ----
        if (t < 256) {
            int k = t & 63, j = t >> 6;
            const float* cp = csrc + k * 64 + j * 16;
            float s = 0.f;
            #pragma unroll
            for (int d = 0; d < 16; d++) s += cp[d] * cp[d];
            sRed[t] = s;
        }
        __syncthreads();
        if (t < 64) sC2[t] = sRed[t] + sRed[64 + t] + sRed[128 + t] + sRed[192 + t];

        float acc2[3][4];
        #pragma unroll
        for (int i = 0; i < 3; i++)
            #pragma unroll
            for (int j = 0; j < 4; j++) acc2[i][j] = 0.f;

        for (int tt = 0; tt < TPB; tt++) {
            int n0 = (bid * TPB + tt) * TILE;
            __syncthreads();   // sEnc/sR reuse safe; sC2/sCH visible on tt=0

            // ---- load enc tile: f32 (gemm2) + bf16 (gemm1) ----
            const float4* eg = reinterpret_cast<const float4*>(enc + (size_t)n0 * D_LAT);
            for (int idx = t; idx < 2048; idx += BLK) {
                int r = idx >> 4, c4 = idx & 15;
                float4 v = eg[idx];
                *reinterpret_cast<float4*>(&sEnc[r * 76 + c4 * 4]) = v;
                uint2 hv = make_uint2(packbf(v.x, v.y), packbf(v.z, v.w));
                *reinterpret_cast<uint2*>(&sEncH[r * 36 + c4 * 2]) = hv;
            }
            __syncthreads();

            if (isCompute) {
                float x2a = sX2[tt * 128 + w * 16 + qr];
                float x2b = sX2[tt * 128 + w * 16 + qr + 8];

                // ---- gemm1 (bf16 m16n8k16): dot[128][64] = enc @ C^T ----
                float acc1[8][4];
                #pragma unroll
                for (int nt = 0; nt < 8; nt++)
                    #pragma unroll
                    for (int j = 0; j < 4; j++) acc1[nt][j] = 0.f;
                {
                    const uint32_t* eH = sEncH + (w * 16 + qr) * 36;
                    #pragma unroll
                    for (int ks = 0; ks < 4; ks++) {
                        uint32_t a0 = eH[ks * 8 + qc];
                        uint32_t a1 = eH[8 * 36 + ks * 8 + qc];
                        uint32_t a2 = eH[ks * 8 + qc + 4];
                        uint32_t a3 = eH[8 * 36 + ks * 8 + qc + 4];
                        const uint32_t* cH = sCH + ks * 8;
                        #pragma unroll
                        for (int nt = 0; nt < 8; nt++) {
                            uint32_t b0 = cH[(nt * 8 + qr) * 36 + qc];
                            uint32_t b1 = cH[(nt * 8 + qr) * 36 + qc + 4];
                            mma_bf16(acc1[nt], a0, a1, a2, a3, b0, b1);
                        }
                    }
                }

                // ---- epilogue on v = 2*dot - c2 (x2 cancels in softmax) ----
                float mx0 = -3.4e38f, mx1 = -3.4e38f;
                #pragma unroll
                for (int nt = 0; nt < 8; nt++) {
                    float c20 = sC2[nt * 8 + qc * 2];
                    float c21 = sC2[nt * 8 + qc * 2 + 1];
                    float v;
                    v = fmaf(2.f, acc1[nt][0], -c20); acc1[nt][0] = v; mx0 = fmaxf(mx0, v);
                    v = fmaf(2.f, acc1[nt][1], -c21); acc1[nt][1] = v; mx0 = fmaxf(mx0, v);
                    v = fmaf(2.f, acc1[nt][2], -c20); acc1[nt][2] = v; mx1 = fmaxf(mx1, v);
                    v = fmaf(2.f, acc1[nt][3], -c21); acc1[nt][3] = v; mx1 = fmaxf(mx1, v);
                }
                mx0 = fmaxf(mx0, __shfl_xor_sync(0xffffffffu, mx0, 1));
                mx0 = fmaxf(mx0, __shfl_xor_sync(0xffffffffu, mx0, 2));
                mx1 = fmaxf(mx1, __shfl_xor_sync(0xffffffffu, mx1, 1));
                mx1 = fmaxf(mx1, __shfl_xor_sync(0xffffffffu, mx1, 2));

                float s0 = 0.f, s1 = 0.f, sl0 = 0.f, sl1 = 0.f;
                #pragma unroll
                for (int nt = 0; nt < 8; nt++) {
                    float v, e;
                    v = acc1[nt][0]; e = __expf(v - mx0); s0 += e; acc1[nt][0] = e;
                    if (doLoss) sl0 += e * fmaxf(x2a - v, 0.f);
                    v = acc1[nt][1]; e = __expf(v - mx0); s0 += e; acc1[nt][1] = e;
                    if (doLoss) sl0 += e * fmaxf(x2a - v, 0.f);
                    v = acc1[nt][2]; e = __expf(v - mx1); s1 += e; acc1[nt][2] = e;
                    if (doLoss) sl1 += e * fmaxf(x2b - v, 0.f);
                    v = acc1[nt][3]; e = __expf(v - mx1); s1 += e; acc1[nt][3] = e;
                    if (doLoss) sl1 += e * fmaxf(x2b - v, 0.f);
                }
                s0 += __shfl_xor_sync(0xffffffffu, s0, 1);  s0 += __shfl_xor_sync(0xffffffffu, s0, 2);
                s1 += __shfl_xor_sync(0xffffffffu, s1, 1);  s1 += __shfl_xor_sync(0xffffffffu, s1, 2);
                float inv0 = 1.f / s0, inv1 = 1.f / s1;
                if (doLoss) {
                    sl0 += __shfl_xor_sync(0xffffffffu, sl0, 1); sl0 += __shfl_xor_sync(0xffffffffu, sl0, 2);
                    sl1 += __shfl_xor_sync(0xffffffffu, sl1, 1); sl1 += __shfl_xor_sync(0xffffffffu, sl1, 2);
                    lossAcc += (sl0 * inv0 + sl1 * inv1) * 0.25f;
                }

                if (doUpdate) {
                    float* r0p = &sR[(w * 16 + qr) * 72];
                    float* r1p = r0p + 8 * 72;
                    #pragma unroll
                    for (int nt = 0; nt < 8; nt++) {
                        int col = nt * 8 + qc * 2;
                        *reinterpret_cast<float2*>(&r0p[col]) = make_float2(acc1[nt][0] * inv0, acc1[nt][1] * inv0);
                        *reinterpret_cast<float2*>(&r1p[col]) = make_float2(acc1[nt][2] * inv1, acc1[nt][3] * inv1);
                    }
                }
            } else {
                // ---- dec-loss streamers: this (it, tt)'s slice ----
                int lo = it * chunk;
                int hi = lo + chunk; if (hi > total4) hi = total4;
                for (int i = lo + bid * 256 + tt * 128 + dt; i < hi; i += GRID_IT * 256) {
                    float4 a = x4[i], b = d4[i];
                    float dx = a.x - b.x, dy = a.y - b.y, dz = a.z - b.z, dw = a.w - b.w;
                    decAcc += dx * dx + dy * dy + dz * dz + dw * dw;
                }
            }
            __syncthreads();

            if (doUpdate) {
                // ---- gemm2 (tf32, all 12 warps): D2[64][72] += r^T @ [enc | 1] ----
                #pragma unroll
                for (int ks = 0; ks < 16; ks++) {
                    const float* rA = sR + (ks * 8 + qc) * 72 + m2 + qr;
                    const float* rB = sR + (ks * 8 + qc + 4) * 72 + m2 + qr;
                    uint32_t a0 = fb(rA[0]);
                    uint32_t a1 = fb(rA[8]);
                    uint32_t a2 = fb(rB[0]);
                    uint32_t a3 = fb(rB[8]);
                    const float* e0 = sEnc + (ks * 8 + qc) * 76 + qr;
                    const float* e1 = sEnc + (ks * 8 + qc + 4) * 76 + qr;
                    #pragma unroll
                    for (int j = 0; j < 3; j++) {
                        int nt = nb2 + 3 * j;
                        uint32_t b0 = fb(e0[nt * 8]);
                        uint32_t b1 = fb(e1[nt * 8]);
                        mma_tf32(acc2[j], a0, a1, a2, a3, b0, b1);
                    }
                }
            }
        }

        if (doUpdate) {
            // ---- write per-block partials ----
            {
                int k0 = m2 + qr, k1 = k0 + 8;
                size_t base = (size_t)bid * 4096;
                #pragma unroll
                for (int j = 0; j < 3; j++) {
                    int nt = nb2 + 3 * j;
                    if (nt < 8) {
                        int d = nt * 8 + qc * 2;
                        *reinterpret_cast<float2*>(&g_partC[base + k0 * 64 + d]) = make_float2(acc2[j][0], acc2[j][1]);
                        *reinterpret_cast<float2*>(&g_partC[base + k1 * 64 + d]) = make_float2(acc2[j][2], acc2[j][3]);
                    } else if (qc == 0) {
                        g_partR[bid * 64 + k0] = acc2[j][0];
                        g_partR[bid * 64 + k1] = acc2[j][2];
                    }
                }
            }
            gridBar();   // all partials visible

            // ---- reduce my 16 C-outputs ----
            {
                int baseo = bid * 16, kk = bid >> 2;
                if (t < 256) {
                    int outc = t & 15, blane = t >> 4;
                    float s = 0.f;
                    #pragma unroll
                    for (int i = 0; i < 16; i++)
                        s += g_partC[(size_t)(blane + i * 16) * 4096 + baseo + outc];
                    sRed[t] = s;
                }
                if (t < 32) {
                    float rs = 0.f;
                    #pragma unroll
                    for (int j = 0; j < 8; j++) rs += g_partR[(t + j * 32) * 64 + kk];
                    #pragma unroll
                    for (int off = 16; off; off >>= 1) rs += __shfl_xor_sync(0xffffffffu, rs, off);
                    if (t == 0) sRed[256] = rs;
                }
                __syncthreads();
                #pragma unroll
                for (int off = 128; off >= 16; off >>= 1) {
                    if (t < off) sRed[t] += sRed[t + off];
                    __syncthreads();
                }
                if (t < 16) g_C[baseo + t] = sRed[t] / (sRed[256] + 1e-8f);
            }
            gridBar();   // g_C complete before next iteration
        }
    }

    // ---- per-block reductions: dec, then loss ----
    __syncthreads();
    sRed[t] = decAcc;
    __syncthreads();
    if (t < 128) sRed[t] += sRed[t + 256];
    __syncthreads();
    for (int off = 128; off; off >>= 1) { if (t < off) sRed[t] += sRed[t + off]; __syncthreads(); }
    if (t == 0) g_decPart[bid] = sRed[0];

    __syncthreads();
    sRed[t] = lossAcc;
    __syncthreads();
    if (t < 128) sRed[t] += sRed[t + 256];
    __syncthreads();
    for (int off = 128; off; off >>= 1) { if (t < off) sRed[t] += sRed[t + off]; __syncthreads(); }
    if (t == 0) g_partLoss[bid] = sRed[0];

    gridBar();

    // ---- block 0: final combine ----
    if (bid == 0) {
        __shared__ double sh[256];
        if (t < 256) sh[t] = (double)g_decPart[t];
        __syncthreads();
        for (int off = 128; off; off >>= 1) { if (t < off) sh[t] += sh[t + off]; __syncthreads(); }
        double decSum = sh[0];
        __syncthreads();
        if (t < 256) sh[t] = (double)g_partLoss[t];
        __syncthreads();
        for (int off = 128; off; off >>= 1) { if (t < off) sh[t] += sh[t + off]; __syncthreads(); }
        if (t == 0) {
            double decLoss = decSum / ((double)N_ROWS * (double)D_DATA);
            double clLoss  = sh[0] / (double)N_ROWS;
            out[0] = (float)(decLoss + 0.001 * clLoss);
        }
    }
}

// ---------------- launch ----------------
extern "C" void kernel_launch(void* const* d_in, const int* in_sizes, int n_in,
                              void* d_out, int out_size) {
    const float* X   = (const float*)d_in[0];
    const float* enc = (const float*)d_in[1];
    const float* dec = (const float*)d_in[2];
    float* out = (float*)d_out;

    const int smemB = SF_TOT * (int)sizeof(float);   // 106240 B
    cudaFuncSetAttribute(fused_kernel, cudaFuncAttributeMaxDynamicSharedMemorySize, smemB);

    fused_kernel<<<GRID_IT, BLK, smemB>>>(enc, X, dec, out);
}